// round 7
// baseline (speedup 1.0000x reference)
#include <cuda_runtime.h>
#include <cuda_bf16.h>
#include <cstdint>

// ShiftKernelMaker: per (b,c) 7x7 slice, emit one-hot (==max) mask.
// Input : float32 [128, 4096, 7, 7]  -> flat 524288 slices x 49 floats
// Output: float32 [524288, 1, 7, 7]  -> same flat layout
//
// R6 -> R7: R6 (one-shot TMA blocks) reached DRAM=66.6% but was latency-
// limited: serial load->wait->compute->store per block. Now: persistent
// blocks, double-buffered smem, software pipeline. While computing tile i
// the TMA load for the block's next tile is already in flight, and stores
// drain asynchronously (bulk_group). 592 blocks (4/SM, smem-bound).

constexpr int KK = 49;                 // 7*7
constexpr int SLICES_PER_BLOCK = 128;  // one slice per thread
constexpr int THREADS = 128;
constexpr int TILE_FLOATS = SLICES_PER_BLOCK * KK;   // 6272
constexpr int TILE_BYTES  = TILE_FLOATS * 4;         // 25088 (16B multiple)
constexpr int SMEM_DYN    = 16 + 2 * TILE_BYTES;     // mbarriers + 2 buffers

__device__ __forceinline__ uint32_t smem_u32(const void* p) {
    uint32_t a;
    asm("{ .reg .u64 t; cvta.to.shared.u64 t, %1; cvt.u32.u64 %0, t; }"
        : "=r"(a) : "l"(p));
    return a;
}

__device__ __forceinline__ void mbar_wait(uint32_t mbar, uint32_t parity) {
    uint32_t done;
    asm volatile(
        "{\n\t"
        ".reg .pred p;\n\t"
        "mbarrier.try_wait.parity.acquire.cta.shared::cta.b64 p, [%1], %2;\n\t"
        "selp.b32 %0, 1, 0, p;\n\t"
        "}" : "=r"(done) : "r"(mbar), "r"(parity) : "memory");
    if (!done) {
        asm volatile(
            "{\n\t"
            ".reg .pred P1;\n\t"
            "WAIT_LOOP_%=:\n\t"
            "mbarrier.try_wait.parity.acquire.cta.shared::cta.b64 P1, [%0], %1, 0x989680;\n\t"
            "@P1 bra.uni WAIT_DONE_%=;\n\t"
            "bra.uni WAIT_LOOP_%=;\n\t"
            "WAIT_DONE_%=:\n\t"
            "}" :: "r"(mbar), "r"(parity) : "memory");
    }
}

__device__ __forceinline__ void tma_load(uint32_t dst, const float* src, uint32_t mbar) {
    asm volatile("mbarrier.arrive.expect_tx.shared.b64 _, [%0], %1;"
                 :: "r"(mbar), "r"(TILE_BYTES) : "memory");
    asm volatile("cp.async.bulk.shared::cluster.global.mbarrier::complete_tx::bytes"
                 " [%0], [%1], %2, [%3];"
                 :: "r"(dst), "l"(src), "r"(TILE_BYTES), "r"(mbar) : "memory");
}

__global__ __launch_bounds__(THREADS)
void shift_mask_kernel(const float* __restrict__ in, float* __restrict__ out,
                       int n_tiles) {
    extern __shared__ char dyn[];
    uint32_t s_base = smem_u32(dyn);
    const uint32_t s_mbar0 = s_base;           // 8 B
    const uint32_t s_mbar1 = s_base + 8;       // 8 B
    const uint32_t s_buf0  = s_base + 16;      // TILE_BYTES
    const uint32_t s_buf1  = s_base + 16 + TILE_BYTES;
    float* buf[2] = { reinterpret_cast<float*>(dyn + 16),
                      reinterpret_cast<float*>(dyn + 16 + TILE_BYTES) };
    const uint32_t s_mbar[2] = { s_mbar0, s_mbar1 };
    const uint32_t s_buf[2]  = { s_buf0, s_buf1 };

    if (threadIdx.x == 0) {
        asm volatile("mbarrier.init.shared.b64 [%0], 1;" :: "r"(s_mbar0) : "memory");
        asm volatile("mbarrier.init.shared.b64 [%0], 1;" :: "r"(s_mbar1) : "memory");
    }
    __syncthreads();

    const int first = blockIdx.x;
    const int stride = gridDim.x;

    // prologue: kick off load of the block's first tile
    if (threadIdx.x == 0 && first < n_tiles) {
        tma_load(s_buf[0], in + (size_t)first * TILE_FLOATS, s_mbar[0]);
    }

    int k = 0;
    for (int i = first; i < n_tiles; i += stride, k++) {
        const int b = k & 1;
        const uint32_t parity = (k >> 1) & 1;   // per-mbar phase

        // wait for this tile's data
        mbar_wait(s_mbar[b], parity);

        // thread0: issue the NEXT load into the other buffer. Before reusing
        // it, drain the store that last read it (only store k-1 can be
        // outstanding here, so wait_group.read 0 waits exactly for it).
        if (threadIdx.x == 0) {
            const int next = i + stride;
            if (next < n_tiles) {
                if (k >= 1)
                    asm volatile("cp.async.bulk.wait_group.read 0;" ::: "memory");
                tma_load(s_buf[1 - b], in + (size_t)next * TILE_FLOATS, s_mbar[1 - b]);
            }
        }

        // compute: per-thread row max, then in-place mask.
        // smem index = tid*49 + j : 49 odd => conflict-free bank permutation.
        {
            float* row = buf[b] + threadIdx.x * KK;
            float mx = row[0];
            #pragma unroll
            for (int j = 1; j < KK; j++) mx = fmaxf(mx, row[j]);
            #pragma unroll
            for (int j = 0; j < KK; j++) row[j] = (row[j] == mx) ? 1.0f : 0.0f;
        }
        __syncthreads();

        // async bulk store; completion handled when the buffer is reused.
        if (threadIdx.x == 0) {
            asm volatile("fence.proxy.async.shared::cta;" ::: "memory");
            asm volatile("cp.async.bulk.global.shared::cta.bulk_group [%0], [%1], %2;"
                         :: "l"(out + (size_t)i * TILE_FLOATS), "r"(s_buf[b]),
                            "r"(TILE_BYTES) : "memory");
            asm volatile("cp.async.bulk.commit_group;" ::: "memory");
        }
    }

    // drain all outstanding stores before CTA exit
    if (threadIdx.x == 0) {
        asm volatile("cp.async.bulk.wait_group 0;" ::: "memory");
    }
}

extern "C" void kernel_launch(void* const* d_in, const int* in_sizes, int n_in,
                              void* d_out, int out_size) {
    const float* in = (const float*)d_in[0];
    float* out = (float*)d_out;

    const int n_elems  = in_sizes[0];                    // 25690112
    const int n_tiles  = n_elems / (KK * SLICES_PER_BLOCK);  // 4096

    cudaFuncSetAttribute(shift_mask_kernel,
                         cudaFuncAttributeMaxDynamicSharedMemorySize, SMEM_DYN);

    int grid = 4 * 148;                                  // 4 CTAs/SM (smem-bound)
    if (grid > n_tiles) grid = n_tiles;

    shift_mask_kernel<<<grid, THREADS, SMEM_DYN>>>(in, out, n_tiles);
}

// round 8
// speedup vs baseline: 1.0668x; 1.0668x over previous
#include <cuda_runtime.h>
#include <cuda_bf16.h>
#include <cstdint>

// ShiftKernelMaker: per (b,c) 7x7 slice, emit one-hot (==max) mask.
// Input : float32 [128, 4096, 7, 7]  -> flat 524288 slices x 49 floats
// Output: float32 [524288, 1, 7, 7]  -> same flat layout
//
// R7 -> R8: the R7 persistent pipeline REGRESSED (4 tiles in flight/SM).
// Back to the R6 one-shot TMA design, but with half-size tiles so ~2x more
// blocks (and thus TMA loads) are resident per SM:
//   64 threads / 64 slices / 12552 B smem -> ~16-18 CTAs/SM vs R6's 8.
// TMA bulk in -> conflict-free scalar smem compute (49 odd => bank
// permutation) -> TMA bulk out. Concurrency comes from resident blocks.

constexpr int KK = 49;                 // 7*7
constexpr int SLICES_PER_BLOCK = 64;   // one slice per thread
constexpr int THREADS = 64;
constexpr int TILE_FLOATS = SLICES_PER_BLOCK * KK;   // 3136
constexpr int TILE_BYTES  = TILE_FLOATS * 4;         // 12544 (16B multiple)

__device__ __forceinline__ uint32_t smem_u32(const void* p) {
    uint32_t a;
    asm("{ .reg .u64 t; cvta.to.shared.u64 t, %1; cvt.u32.u64 %0, t; }"
        : "=r"(a) : "l"(p));
    return a;
}

__global__ __launch_bounds__(THREADS, 16)
void shift_mask_kernel(const float* __restrict__ in, float* __restrict__ out) {
    __shared__ alignas(16) float tile[TILE_FLOATS];
    __shared__ alignas(8)  uint64_t mbar;

    const size_t base = (size_t)blockIdx.x * TILE_FLOATS;
    const uint32_t s_tile = smem_u32(tile);
    const uint32_t s_mbar = smem_u32(&mbar);

    // ---- TMA bulk load: global -> smem (single issuing thread) ----
    if (threadIdx.x == 0) {
        asm volatile("mbarrier.init.shared.b64 [%0], 1;" :: "r"(s_mbar) : "memory");
    }
    __syncthreads();
    if (threadIdx.x == 0) {
        asm volatile("mbarrier.arrive.expect_tx.shared.b64 _, [%0], %1;"
                     :: "r"(s_mbar), "r"(TILE_BYTES) : "memory");
        asm volatile("cp.async.bulk.shared::cluster.global.mbarrier::complete_tx::bytes"
                     " [%0], [%1], %2, [%3];"
                     :: "r"(s_tile), "l"(in + base), "r"(TILE_BYTES), "r"(s_mbar)
                     : "memory");
    }

    // ---- wait for TMA completion (parity 0, acquire) ----
    {
        uint32_t done;
        asm volatile(
            "{\n\t"
            ".reg .pred p;\n\t"
            "mbarrier.try_wait.parity.acquire.cta.shared::cta.b64 p, [%1], 0;\n\t"
            "selp.b32 %0, 1, 0, p;\n\t"
            "}" : "=r"(done) : "r"(s_mbar) : "memory");
        if (!done) {
            asm volatile(
                "{\n\t"
                ".reg .pred P1;\n\t"
                "WAIT_LOOP_%=:\n\t"
                "mbarrier.try_wait.parity.acquire.cta.shared::cta.b64 P1, [%0], 0, 0x989680;\n\t"
                "@P1 bra.uni WAIT_DONE_%=;\n\t"
                "bra.uni WAIT_LOOP_%=;\n\t"
                "WAIT_DONE_%=:\n\t"
                "}" :: "r"(s_mbar) : "memory");
        }
    }

    // ---- compute: per-thread row max, then in-place mask ----
    // smem index = tid*49 + i : 49 odd => conflict-free bank permutation.
    {
        float* row = tile + threadIdx.x * KK;
        float mx = row[0];
        #pragma unroll
        for (int i = 1; i < KK; i++) mx = fmaxf(mx, row[i]);
        #pragma unroll
        for (int i = 0; i < KK; i++) row[i] = (row[i] == mx) ? 1.0f : 0.0f;
    }
    __syncthreads();

    // ---- TMA bulk store: smem -> global ----
    asm volatile("fence.proxy.async.shared::cta;" ::: "memory");
    if (threadIdx.x == 0) {
        asm volatile("cp.async.bulk.global.shared::cta.bulk_group [%0], [%1], %2;"
                     :: "l"(out + base), "r"(s_tile), "r"(TILE_BYTES) : "memory");
        asm volatile("cp.async.bulk.commit_group;" ::: "memory");
        asm volatile("cp.async.bulk.wait_group.read 0;" ::: "memory");
    }
}

extern "C" void kernel_launch(void* const* d_in, const int* in_sizes, int n_in,
                              void* d_out, int out_size) {
    const float* in = (const float*)d_in[0];
    float* out = (float*)d_out;

    const int n_elems  = in_sizes[0];                    // 25690112
    const int n_slices = n_elems / KK;                   // 524288
    const int grid     = n_slices / SLICES_PER_BLOCK;    // 8192 (exact)

    shift_mask_kernel<<<grid, THREADS>>>(in, out);
}